// round 2
// baseline (speedup 1.0000x reference)
#include <cuda_runtime.h>

#define NS (1<<20)

// ---- device scratch (static, allocation-free) ----
__device__ float g_T0[NS];
__device__ float g_T1[NS];
__device__ float g_A[NS];    // A[P01][bond]  (1024x1024)
__device__ float g_Cm[NS];   // C[bond][P23]  (1024x1024)
__device__ float g_psi[NS];  // statevector ping
__device__ float g_R[1024];  // 32x32 row-chain operator, row-major [out][in]
__device__ float g_C16[256]; // 16x16 column-chain operator

__device__ __forceinline__ float peps_el(const float* __restrict__ peps,
                                         int i,int j,int p,int u,int d,int l,int r){
    // shape (4,5,2,4,4,4,4)
    return peps[(((((i*5+j)*2+p)*4+u)*4+d)*4+l)*4+r];
}

// ------------- build R (32x32) and C16 (16x16) from the 4x4 gate -------------
__global__ void build_rc_kernel(const float* __restrict__ gate){
    __shared__ float g[16];
    __shared__ float A0[1024];
    __shared__ float A1[1024];
    int t = threadIdx.x;                       // 1024 threads
    if (t < 16) g[t] = gate[t];
    A0[t] = ((t>>5)==(t&31)) ? 1.0f : 0.0f;    // R = I (32x32)
    __syncthreads();
    // horizontal chain: gate on local sites (k,k+1); site k at bit (4-k). R <- G_k @ R
    #pragma unroll
    for (int k=0;k<4;k++){
        const float* cur = (k&1)? A1 : A0;
        float* nxt       = (k&1)? A0 : A1;
        int hb = 4-k, lb = 3-k;
        int rp = t>>5, c = t&31;
        int i1p=(rp>>hb)&1, i2p=(rp>>lb)&1;
        int base = rp & ~((1<<hb)|(1<<lb));
        float acc=0.f;
        #pragma unroll
        for(int i1=0;i1<2;i1++)
        #pragma unroll
        for(int i2=0;i2<2;i2++)
            acc += g[(i1p*2+i2p)*4+(i1*2+i2)] * cur[(base|(i1<<hb)|(i2<<lb))*32 + c];
        __syncthreads();
        nxt[t]=acc;
        __syncthreads();
    }
    g_R[t]=A0[t];  // 4 ping-pongs end in A0
    __syncthreads();
    // vertical chain: 4 bits, row r at bit (3-r); gates (0,1),(1,2),(2,3) in order
    if (t<256) A0[t] = ((t>>4)==(t&15)) ? 1.0f : 0.0f;
    __syncthreads();
    #pragma unroll
    for (int k=0;k<3;k++){
        const float* cur=(k&1)?A1:A0;
        float* nxt      =(k&1)?A0:A1;
        float acc=0.f;
        if (t<256){
            int hb=3-k, lb=2-k;
            int rp=t>>4, c=t&15;
            int i1p=(rp>>hb)&1,i2p=(rp>>lb)&1;
            int base = rp & ~((1<<hb)|(1<<lb));
            #pragma unroll
            for(int i1=0;i1<2;i1++)
            #pragma unroll
            for(int i2=0;i2<2;i2++)
                acc += g[(i1p*2+i2p)*4+(i1*2+i2)]*cur[(base|(i1<<hb)|(i2<<lb))*16+c];
        }
        __syncthreads();
        if (t<256) nxt[t]=acc;
        __syncthreads();
    }
    if (t<256) g_C16[t]=A1[t];  // 3 ping-pongs end in A1
}

// ------------- fold rows 0&1 column-by-column into A -------------
// T_j layout: [a(2^j)][b(2^j)][c(4^j)][l0(L)][l1(L)]
__global__ void afold_kernel(const float* __restrict__ peps, int j){
    const float* Tin = (j&1)? g_T1 : g_T0;
    float* Tout = (j==4)? g_A : ((j&1)? g_T0 : g_T1);
    int L = (j==0)?1:4;
    int R = (j==4)?1:4;
    int twoJ = 1<<j;
    int fourJ = 1<<(2*j);
    int twoJ2 = twoJ<<1;
    int fourJ2 = fourJ<<2;
    long nout = (long)twoJ2*twoJ2*fourJ2*R*R;

    __shared__ float K[4096];
    int nk = 2*2*4*L*L*R*R;
    for (int e=threadIdx.x; e<nk; e+=blockDim.x){
        int tt=e;
        int r1=tt%R; tt/=R; int r0=tt%R; tt/=R;
        int l1=tt%L; tt/=L; int l0=tt%L; tt/=L;
        int d1=tt&3; tt>>=2;
        int p1=tt&1; int p0=tt>>1;
        float s=0.f;
        #pragma unroll
        for(int m=0;m<4;m++)
            s += peps_el(peps,0,j,p0,0,m,l0,r0)*peps_el(peps,1,j,p1,m,d1,l1,r1);
        K[e]=s;
    }
    __syncthreads();

    long tid = (long)blockIdx.x*blockDim.x + threadIdx.x;
    if (tid>=nout) return;
    long t=tid;
    int r1 = (int)(t % R); t/=R;
    int r0 = (int)(t % R); t/=R;
    int cp = (int)(t % fourJ2); t/=fourJ2;
    int bp = (int)(t % twoJ2); t/=twoJ2;
    int ap = (int)t;
    int p0 = ap&1, a=ap>>1;
    int p1 = bp&1, b=bp>>1;
    int d1 = cp&3, c=cp>>2;
    int kb = (p0*2+p1)*4+d1;
    float acc=0.f;
    for(int l0=0;l0<L;l0++){
        for(int l1=0;l1<L;l1++){
            float tv = (j==0)? 1.0f
                : Tin[ (((long)((long)a*twoJ+b)*fourJ + c)*L + l0)*L + l1 ];
            acc += tv * K[ ((kb*L+l0)*L+l1)*R*R + r0*R + r1 ];
        }
    }
    Tout[tid]=acc;
}

// ------------- fold rows 2&3 into C -------------
// G_j layout: [c(4^j)][a(2^j)][b(2^j)][l2(L)][l3(L)]
__global__ void cfold_kernel(const float* __restrict__ peps, int j){
    const float* Tin = (j&1)? g_T1 : g_T0;
    float* Tout = (j==4)? g_Cm : ((j&1)? g_T0 : g_T1);
    int L = (j==0)?1:4;
    int R = (j==4)?1:4;
    int twoJ = 1<<j;
    int fourJ = 1<<(2*j);
    int twoJ2 = twoJ<<1;
    int fourJ2 = fourJ<<2;
    long nout = (long)twoJ2*twoJ2*fourJ2*R*R;

    __shared__ float K[4096];
    int nk = 2*2*4*L*L*R*R;
    for (int e=threadIdx.x; e<nk; e+=blockDim.x){
        int tt=e;
        int r3=tt%R; tt/=R; int r2=tt%R; tt/=R;
        int l3=tt%L; tt/=L; int l2=tt%L; tt/=L;
        int u2=tt&3; tt>>=2;
        int p3=tt&1; int p2=tt>>1;
        float s=0.f;
        #pragma unroll
        for(int m=0;m<4;m++)
            s += peps_el(peps,2,j,p2,u2,m,l2,r2)*peps_el(peps,3,j,p3,m,0,l3,r3);
        K[e]=s;
    }
    __syncthreads();

    long tid = (long)blockIdx.x*blockDim.x + threadIdx.x;
    if (tid>=nout) return;
    long t=tid;
    int r3 = (int)(t % R); t/=R;
    int r2 = (int)(t % R); t/=R;
    int bp = (int)(t % twoJ2); t/=twoJ2;
    int ap = (int)(t % twoJ2); t/=twoJ2;
    int cp = (int)t;
    int p2 = ap&1, a=ap>>1;
    int p3 = bp&1, b=bp>>1;
    int u2 = cp&3, c=cp>>2;
    int kb = (p2*2+p3)*4+u2;
    float acc=0.f;
    for(int l2=0;l2<L;l2++){
        for(int l3=0;l3<L;l3++){
            float tv = (j==0)? 1.0f
                : Tin[ (((long)((long)c*twoJ+a)*twoJ + b)*L + l2)*L + l3 ];
            acc += tv * K[ ((kb*L+l2)*L+l3)*R*R + r2*R + r3 ];
        }
    }
    Tout[tid]=acc;
}

// ------------- psi = A(1024x1024) @ C(1024x1024) -------------
__global__ __launch_bounds__(256) void sgemm_kernel(const float* __restrict__ A,
        const float* __restrict__ B, float* __restrict__ Cout){
    __shared__ float As[16][65];
    __shared__ float Bs[16][64];
    int bx=blockIdx.x, by=blockIdx.y;
    int tid=threadIdx.x;
    int tx=tid&15, ty=tid>>4;           // 16x16 threads, 4x4 micro-tile
    float acc[4][4];
    #pragma unroll
    for(int i=0;i<4;i++)
      #pragma unroll
      for(int jj=0;jj<4;jj++) acc[i][jj]=0.f;

    const float* Ablk = A + (long)(by*64)*1024;
    const float* Bblk = B + bx*64;
    for (int k0=0;k0<1024;k0+=16){
        #pragma unroll
        for (int e=0;e<4;e++){
            int idx = tid + e*256;
            int m = idx>>4, k = idx&15;
            As[k][m] = Ablk[(long)m*1024 + k0 + k];
        }
        #pragma unroll
        for (int e=0;e<4;e++){
            int idx = tid + e*256;
            int k = idx>>6, n = idx&63;
            Bs[k][n] = Bblk[(long)(k0+k)*1024 + n];
        }
        __syncthreads();
        #pragma unroll
        for (int k=0;k<16;k++){
            float a0=As[k][ty*4+0], a1=As[k][ty*4+1];
            float a2=As[k][ty*4+2], a3=As[k][ty*4+3];
            float b0=Bs[k][tx*4+0], b1=Bs[k][tx*4+1];
            float b2=Bs[k][tx*4+2], b3=Bs[k][tx*4+3];
            acc[0][0]+=a0*b0; acc[0][1]+=a0*b1; acc[0][2]+=a0*b2; acc[0][3]+=a0*b3;
            acc[1][0]+=a1*b0; acc[1][1]+=a1*b1; acc[1][2]+=a1*b2; acc[1][3]+=a1*b3;
            acc[2][0]+=a2*b0; acc[2][1]+=a2*b1; acc[2][2]+=a2*b2; acc[2][3]+=a2*b3;
            acc[3][0]+=a3*b0; acc[3][1]+=a3*b1; acc[3][2]+=a3*b2; acc[3][3]+=a3*b3;
        }
        __syncthreads();
    }
    #pragma unroll
    for(int i=0;i<4;i++)
      #pragma unroll
      for(int jj=0;jj<4;jj++)
        Cout[(long)(by*64+ty*4+i)*1024 + bx*64+tx*4+jj]=acc[i][jj];
}

// ------------- horizontal mode-product: apply R to 5 contiguous bits at 'shift' -------------
// 2 threads per fiber (16 outputs each), 65536 threads total.
__global__ __launch_bounds__(256) void hmode_kernel(const float* __restrict__ in,
        float* __restrict__ out, int shift){
    __shared__ float Rs[1024];
    int tid=threadIdx.x;
    for(int e=tid;e<1024;e+=256) Rs[e]=g_R[e];
    __syncthreads();
    unsigned t = blockIdx.x*256u + (unsigned)tid;
    unsigned f = t>>1;                      // fiber 0..32767
    int obase = (int)(t&1)*16;
    unsigned low  = f & ((1u<<shift)-1u);
    unsigned base = ((f>>shift)<<(shift+5)) | low;
    unsigned s = 1u<<shift;
    float v[32];
    #pragma unroll
    for(int i=0;i<32;i++) v[i]=in[base + (unsigned)i*s];
    #pragma unroll 4
    for(int o=0;o<16;o++){
        float a0=0.f,a1=0.f,a2=0.f,a3=0.f;
        #pragma unroll
        for(int i=0;i<32;i+=4){
            const float* rr = &Rs[(obase+o)*32+i];
            a0+=rr[0]*v[i+0]; a1+=rr[1]*v[i+1];
            a2+=rr[2]*v[i+2]; a3+=rr[3]*v[i+3];
        }
        out[base + (unsigned)(obase+o)*s] = (a0+a1)+(a2+a3);
    }
}

// ------------- vertical mode-product: apply C16 to bits {p, p+5, p+10, p+15} -------------
__global__ __launch_bounds__(256) void vmode_kernel(const float* __restrict__ in,
        float* __restrict__ out, int p){
    __shared__ float Cs[256];
    int tid=threadIdx.x;
    if (tid<256) Cs[tid]=g_C16[tid];
    __syncthreads();
    unsigned f = blockIdx.x*256u + (unsigned)tid;   // 0..65535
    // scatter f's 16 bits around mode positions p, p+5, p+10, p+15 (ascending)
    unsigned tt=f;
    tt = ((tt >> p)      << (p+1))  | (tt & ((1u<<p)-1u));
    tt = ((tt >> (p+5))  << (p+6))  | (tt & ((1u<<(p+5))-1u));
    tt = ((tt >> (p+10)) << (p+11)) | (tt & ((1u<<(p+10))-1u));
    tt = ((tt >> (p+15)) << (p+16)) | (tt & ((1u<<(p+15))-1u));
    unsigned base=tt;
    unsigned s0=1u<<p, s1=1u<<(p+5), s2=1u<<(p+10), s3=1u<<(p+15);
    float v[16];
    #pragma unroll
    for(int i=0;i<16;i++){
        unsigned a = base + (i&1)*s0 + ((i>>1)&1)*s1 + ((i>>2)&1)*s2 + ((i>>3)&1)*s3;
        v[i]=in[a];
    }
    #pragma unroll 4
    for(int o=0;o<16;o++){
        float acc0=0.f, acc1=0.f;
        #pragma unroll
        for(int i=0;i<16;i+=2){
            acc0 += Cs[o*16+i]  *v[i];
            acc1 += Cs[o*16+i+1]*v[i+1];
        }
        unsigned a = base + (o&1)*s0 + ((o>>1)&1)*s1 + ((o>>2)&1)*s2 + ((o>>3)&1)*s3;
        out[a]=acc0+acc1;
    }
}

// ------------- gather 64 amplitudes -------------
__global__ void gather_kernel(const int* __restrict__ x, const float* __restrict__ psi,
                              float* __restrict__ out){
    int b = threadIdx.x; // 64
    unsigned idx=0;
    #pragma unroll
    for (int j=0;j<20;j++) idx = (idx<<1) | (unsigned)x[b*20+j];
    out[b]=psi[idx];
}

extern "C" void kernel_launch(void* const* d_in, const int* in_sizes, int n_in,
                              void* d_out, int out_size){
    const int*   x    = (const int*)d_in[0];
    const float* peps = (const float*)d_in[1];
    const float* gate = (const float*)d_in[2];
    float* out = (float*)d_out;

    float *A,*Cm,*psi,*psi2;
    cudaGetSymbolAddress((void**)&A,    g_A);
    cudaGetSymbolAddress((void**)&Cm,   g_Cm);
    cudaGetSymbolAddress((void**)&psi,  g_psi);
    cudaGetSymbolAddress((void**)&psi2, g_T0);  // reuse scratch after folds

    build_rc_kernel<<<1,1024>>>(gate);

    for (int j=0;j<5;j++){
        int twoJ2 = 2<<j;
        int fourJ2 = 4<<(2*j);
        int R = (j==4)?1:4;
        long nout = (long)twoJ2*twoJ2*fourJ2*R*R;
        int nb = (int)((nout+255)/256);
        afold_kernel<<<nb,256>>>(peps,j);
    }
    for (int j=0;j<5;j++){
        int twoJ2 = 2<<j;
        int fourJ2 = 4<<(2*j);
        int R = (j==4)?1:4;
        long nout = (long)twoJ2*twoJ2*fourJ2*R*R;
        int nb = (int)((nout+255)/256);
        cfold_kernel<<<nb,256>>>(peps,j);
    }

    sgemm_kernel<<<dim3(16,16),256>>>(A, Cm, psi);

    float* cur = psi;
    float* nxt = psi2;
    const int shifts[4] = {15,10,5,0};
    for (int sweep=0; sweep<5; sweep++){
        for (int h=0;h<4;h++){
            hmode_kernel<<<256,256>>>(cur, nxt, shifts[h]);
            float* tmp=cur; cur=nxt; nxt=tmp;
        }
        for (int j=0;j<5;j++){
            vmode_kernel<<<256,256>>>(cur, nxt, 4-j);
            float* tmp=cur; cur=nxt; nxt=tmp;
        }
    }

    gather_kernel<<<1,64>>>(x, cur, out);
}

// round 3
// speedup vs baseline: 1.1708x; 1.1708x over previous
#include <cuda_runtime.h>

#define NS (1<<20)

// ---- device scratch (static, allocation-free) ----
__device__ float g_T0[NS];
__device__ float g_T1[NS];
__device__ float g_A[NS];    // A[P01][bond]  (1024x1024)
__device__ float g_Cm[NS];   // C[bond][P23]  (1024x1024)
__device__ float g_psi[NS];  // statevector (in-place for sweeps)
__device__ float g_R[1024];  // 32x32 row-chain operator, row-major [out][in]
__device__ float g_C16[256]; // 16x16 column-chain operator
__device__ float g_K[10*4096]; // precomputed per-column pair tensors

__device__ __forceinline__ float peps_el(const float* __restrict__ peps,
                                         int i,int j,int p,int u,int d,int l,int r){
    return peps[(((((i*5+j)*2+p)*4+u)*4+d)*4+l)*4+r];
}

// ------------- build R (32x32) and C16 (16x16) -------------
__global__ void build_rc_kernel(const float* __restrict__ gate){
    __shared__ float g[16];
    __shared__ float A0[1024];
    __shared__ float A1[1024];
    int t = threadIdx.x;
    if (t < 16) g[t] = gate[t];
    A0[t] = ((t>>5)==(t&31)) ? 1.0f : 0.0f;
    __syncthreads();
    #pragma unroll
    for (int k=0;k<4;k++){
        const float* cur = (k&1)? A1 : A0;
        float* nxt       = (k&1)? A0 : A1;
        int hb = 4-k, lb = 3-k;
        int rp = t>>5, c = t&31;
        int i1p=(rp>>hb)&1, i2p=(rp>>lb)&1;
        int base = rp & ~((1<<hb)|(1<<lb));
        float acc=0.f;
        #pragma unroll
        for(int i1=0;i1<2;i1++)
        #pragma unroll
        for(int i2=0;i2<2;i2++)
            acc += g[(i1p*2+i2p)*4+(i1*2+i2)] * cur[(base|(i1<<hb)|(i2<<lb))*32 + c];
        __syncthreads();
        nxt[t]=acc;
        __syncthreads();
    }
    g_R[t]=A0[t];
    __syncthreads();
    if (t<256) A0[t] = ((t>>4)==(t&15)) ? 1.0f : 0.0f;
    __syncthreads();
    #pragma unroll
    for (int k=0;k<3;k++){
        const float* cur=(k&1)?A1:A0;
        float* nxt      =(k&1)?A0:A1;
        float acc=0.f;
        if (t<256){
            int hb=3-k, lb=2-k;
            int rp=t>>4, c=t&15;
            int i1p=(rp>>hb)&1,i2p=(rp>>lb)&1;
            int base = rp & ~((1<<hb)|(1<<lb));
            #pragma unroll
            for(int i1=0;i1<2;i1++)
            #pragma unroll
            for(int i2=0;i2<2;i2++)
                acc += g[(i1p*2+i2p)*4+(i1*2+i2)]*cur[(base|(i1<<hb)|(i2<<lb))*16+c];
        }
        __syncthreads();
        if (t<256) nxt[t]=acc;
        __syncthreads();
    }
    if (t<256) g_C16[t]=A1[t];
}

// ------------- precompute K tensors for all 10 folds -------------
__global__ void kprep_kernel(const float* __restrict__ peps){
    int blk = blockIdx.x;        // 0..9 : pair*5 + j
    int pair = blk/5, j = blk%5;
    int L = (j==0)?1:4, R = (j==4)?1:4;
    int nk = 16*L*L*R*R;
    float* Kg = g_K + blk*4096;
    for (int e=threadIdx.x; e<nk; e+=blockDim.x){
        int tt=e;
        int rb=tt%R; tt/=R; int ra=tt%R; tt/=R;
        int lb=tt%L; tt/=L; int la=tt%L; tt/=L;
        int mid=tt&3; tt>>=2;
        int pb=tt&1; int pa=tt>>1;
        float s=0.f;
        if (pair==0){
            #pragma unroll
            for(int m=0;m<4;m++)
                s += peps_el(peps,0,j,pa,0,m,la,ra)*peps_el(peps,1,j,pb,m,mid,lb,rb);
        } else {
            #pragma unroll
            for(int m=0;m<4;m++)
                s += peps_el(peps,2,j,pa,mid,m,la,ra)*peps_el(peps,3,j,pb,m,0,lb,rb);
        }
        Kg[e]=s;
    }
}

// ------------- fold rows 0&1 into A -------------
__global__ void afold_kernel(int j){
    const float* Tin = (j&1)? g_T1 : g_T0;
    float* Tout = (j==4)? g_A : ((j&1)? g_T0 : g_T1);
    int L = (j==0)?1:4;
    int R = (j==4)?1:4;
    int twoJ = 1<<j;
    int fourJ = 1<<(2*j);
    int twoJ2 = twoJ<<1;
    int fourJ2 = fourJ<<2;
    long nout = (long)twoJ2*twoJ2*fourJ2*R*R;

    __shared__ float K[4096];
    int nk = 16*L*L*R*R;
    const float* Kg = g_K + (0*5+j)*4096;
    for (int e=threadIdx.x; e<nk; e+=blockDim.x) K[e]=Kg[e];
    __syncthreads();

    long tid = (long)blockIdx.x*blockDim.x + threadIdx.x;
    if (tid>=nout) return;
    long t=tid;
    int r1 = (int)(t % R); t/=R;
    int r0 = (int)(t % R); t/=R;
    int cp = (int)(t % fourJ2); t/=fourJ2;
    int bp = (int)(t % twoJ2); t/=twoJ2;
    int ap = (int)t;
    int p0 = ap&1, a=ap>>1;
    int p1 = bp&1, b=bp>>1;
    int d1 = cp&3, c=cp>>2;
    int kb = (p0*2+p1)*4+d1;
    float acc=0.f;
    for(int l0=0;l0<L;l0++){
        for(int l1=0;l1<L;l1++){
            float tv = (j==0)? 1.0f
                : Tin[ (((long)((long)a*twoJ+b)*fourJ + c)*L + l0)*L + l1 ];
            acc += tv * K[ ((kb*L+l0)*L+l1)*R*R + r0*R + r1 ];
        }
    }
    Tout[tid]=acc;
}

// ------------- fold rows 2&3 into C -------------
__global__ void cfold_kernel(int j){
    const float* Tin = (j&1)? g_T1 : g_T0;
    float* Tout = (j==4)? g_Cm : ((j&1)? g_T0 : g_T1);
    int L = (j==0)?1:4;
    int R = (j==4)?1:4;
    int twoJ = 1<<j;
    int fourJ = 1<<(2*j);
    int twoJ2 = twoJ<<1;
    int fourJ2 = fourJ<<2;
    long nout = (long)twoJ2*twoJ2*fourJ2*R*R;

    __shared__ float K[4096];
    int nk = 16*L*L*R*R;
    const float* Kg = g_K + (1*5+j)*4096;
    for (int e=threadIdx.x; e<nk; e+=blockDim.x) K[e]=Kg[e];
    __syncthreads();

    long tid = (long)blockIdx.x*blockDim.x + threadIdx.x;
    if (tid>=nout) return;
    long t=tid;
    int r3 = (int)(t % R); t/=R;
    int r2 = (int)(t % R); t/=R;
    int bp = (int)(t % twoJ2); t/=twoJ2;
    int ap = (int)(t % twoJ2); t/=twoJ2;
    int cp = (int)t;
    int p2 = ap&1, a=ap>>1;
    int p3 = bp&1, b=bp>>1;
    int u2 = cp&3, c=cp>>2;
    int kb = (p2*2+p3)*4+u2;
    float acc=0.f;
    for(int l2=0;l2<L;l2++){
        for(int l3=0;l3<L;l3++){
            float tv = (j==0)? 1.0f
                : Tin[ (((long)((long)c*twoJ+a)*twoJ + b)*L + l2)*L + l3 ];
            acc += tv * K[ ((kb*L+l2)*L+l3)*R*R + r2*R + r3 ];
        }
    }
    Tout[tid]=acc;
}

// ------------- psi = A(1024x1024) @ C(1024x1024) -------------
__global__ __launch_bounds__(256) void sgemm_kernel(const float* __restrict__ A,
        const float* __restrict__ B, float* __restrict__ Cout){
    __shared__ float As[16][65];
    __shared__ float Bs[16][64];
    int bx=blockIdx.x, by=blockIdx.y;
    int tid=threadIdx.x;
    int tx=tid&15, ty=tid>>4;
    float acc[4][4];
    #pragma unroll
    for(int i=0;i<4;i++)
      #pragma unroll
      for(int jj=0;jj<4;jj++) acc[i][jj]=0.f;

    const float* Ablk = A + (long)(by*64)*1024;
    const float* Bblk = B + bx*64;
    for (int k0=0;k0<1024;k0+=16){
        #pragma unroll
        for (int e=0;e<4;e++){
            int idx = tid + e*256;
            int m = idx>>4, k = idx&15;
            As[k][m] = Ablk[(long)m*1024 + k0 + k];
        }
        #pragma unroll
        for (int e=0;e<4;e++){
            int idx = tid + e*256;
            int k = idx>>6, n = idx&63;
            Bs[k][n] = Bblk[(long)(k0+k)*1024 + n];
        }
        __syncthreads();
        #pragma unroll
        for (int k=0;k<16;k++){
            float a0=As[k][ty*4+0], a1=As[k][ty*4+1];
            float a2=As[k][ty*4+2], a3=As[k][ty*4+3];
            float b0=Bs[k][tx*4+0], b1=Bs[k][tx*4+1];
            float b2=Bs[k][tx*4+2], b3=Bs[k][tx*4+3];
            acc[0][0]+=a0*b0; acc[0][1]+=a0*b1; acc[0][2]+=a0*b2; acc[0][3]+=a0*b3;
            acc[1][0]+=a1*b0; acc[1][1]+=a1*b1; acc[1][2]+=a1*b2; acc[1][3]+=a1*b3;
            acc[2][0]+=a2*b0; acc[2][1]+=a2*b1; acc[2][2]+=a2*b2; acc[2][3]+=a2*b3;
            acc[3][0]+=a3*b0; acc[3][1]+=a3*b1; acc[3][2]+=a3*b2; acc[3][3]+=a3*b3;
        }
        __syncthreads();
    }
    #pragma unroll
    for(int i=0;i<4;i++)
      #pragma unroll
      for(int jj=0;jj<4;jj++)
        Cout[(long)(by*64+ty*4+i)*1024 + bx*64+tx*4+jj]=acc[i][jj];
}

// ------------- fused horizontal low: bits [5-9] and [0-4], in-place -------------
__global__ __launch_bounds__(256) void hlow_kernel(float* __restrict__ psi){
    __shared__ float T[32][33];
    __shared__ float Usm[32][33];
    __shared__ float Rs[1024];   // R[out][in]
    __shared__ float RsT[1024];  // R[in][out]
    int tid=threadIdx.x;
    for (int e=tid;e<1024;e+=256){
        float v = g_R[e];
        Rs[e]=v;
        RsT[(e&31)*32 + (e>>5)] = v;
    }
    unsigned base = blockIdx.x*1024u;
    #pragma unroll
    for (int it=0;it<4;it++){
        int e = tid + it*256;
        T[e>>5][e&31] = psi[base+e];
    }
    __syncthreads();
    int rp = tid & 31, cq = tid >> 5;
    float u[4]={0.f,0.f,0.f,0.f};
    for (int r=0;r<32;r++){
        float rv = RsT[r*32+rp];   // = R[rp][r], conflict-free across lanes
        #pragma unroll
        for (int i=0;i<4;i++) u[i] += rv * T[r][cq*4+i];
    }
    #pragma unroll
    for (int i=0;i<4;i++) Usm[rp][cq*4+i]=u[i];
    __syncthreads();
    float w[4];
    #pragma unroll
    for (int i=0;i<4;i++){
        int cp = cq*4+i;
        float acc=0.f;
        #pragma unroll
        for (int c=0;c<32;c++) acc += Rs[cp*32+c]*Usm[rp][c];
        w[i]=acc;
    }
    __syncthreads();
    #pragma unroll
    for (int i=0;i<4;i++) T[rp][cq*4+i]=w[i];
    __syncthreads();
    #pragma unroll
    for (int it=0;it<4;it++){
        int e = tid + it*256;
        psi[base+e] = T[e>>5][e&31];
    }
}

// ------------- fused horizontal high: bits [15-19] and [10-14], in-place -------------
__global__ __launch_bounds__(256) void hhigh_kernel(float* __restrict__ psi){
    __shared__ float S[8][1036];
    __shared__ float Rs[1024];
    __shared__ float RsT[1024];
    int tid = threadIdx.x;
    for (int e=tid;e<1024;e+=256){
        float v = g_R[e];
        Rs[e]=v;
        RsT[(e&31)*32 + (e>>5)] = v;
    }
    unsigned lowbase = blockIdx.x * 8u;
    for (int it=0; it<32; it++){
        int idx = tid + it*256;
        int lo = idx & 7, k = idx >> 3;
        S[lo][k] = psi[(unsigned)k*1024u + lowbase + (unsigned)lo];
    }
    __syncthreads();
    int low = tid & 7, rp = tid >> 3;   // rp = output row (bits 15-19)
    float U[32];
    #pragma unroll
    for (int c=0;c<32;c++) U[c]=0.f;
    for (int r=0;r<32;r++){
        float rv = RsT[r*32+rp];
        const float4* row = (const float4*)&S[low][r*32];
        #pragma unroll
        for (int c4=0;c4<8;c4++){
            float4 t = row[c4];
            U[c4*4+0] += rv*t.x; U[c4*4+1] += rv*t.y;
            U[c4*4+2] += rv*t.z; U[c4*4+3] += rv*t.w;
        }
    }
    float W[32];
    #pragma unroll
    for (int cp=0;cp<32;cp++){
        float acc=0.f;
        #pragma unroll
        for (int c=0;c<32;c++) acc += Rs[cp*32+c]*U[c];
        W[cp]=acc;
    }
    __syncthreads();
    #pragma unroll
    for (int cp=0;cp<32;cp++) S[low][rp*32+cp] = W[cp];
    __syncthreads();
    for (int it=0; it<32; it++){
        int idx = tid + it*256;
        int lo = idx & 7, k = idx >> 3;
        psi[(unsigned)k*1024u + lowbase + (unsigned)lo] = S[lo][k];
    }
}

// ------------- fused vertical: columns p and p+1, in-place -------------
__global__ __launch_bounds__(256) void v2_kernel(float* __restrict__ psi, int p){
    __shared__ float Cs[256];
    __shared__ float Tsm[8][16][17];
    __shared__ float Usm[8][16][17];
    int tid=threadIdx.x;
    if (tid<256) Cs[tid]=g_C16[tid];
    int w = tid>>5, l = tid&31;
    unsigned f = blockIdx.x*8u + (unsigned)w;   // 12-bit fiber id
    unsigned tt=f;
    tt = ((tt>>p)<<(p+2))        | (tt & ((1u<<p)-1u));
    tt = ((tt>>(p+5))<<(p+7))    | (tt & ((1u<<(p+5))-1u));
    tt = ((tt>>(p+10))<<(p+12))  | (tt & ((1u<<(p+10))-1u));
    tt = ((tt>>(p+15))<<(p+17))  | (tt & ((1u<<(p+15))-1u));
    unsigned base=tt;
    __syncthreads();
    unsigned offs[8];
    #pragma unroll
    for (int t=0;t<8;t++){
        int e = l + 32*t;
        int i0 = e & 15, i1 = e >> 4;
        unsigned off =
            (unsigned)(((i0&1)|((i1&1)<<1)) << p) |
            (unsigned)((((i0>>1)&1)|(((i1>>1)&1)<<1)) << (p+5)) |
            (unsigned)((((i0>>2)&1)|(((i1>>2)&1)<<1)) << (p+10)) |
            (unsigned)((((i0>>3)&1)|(((i1>>3)&1)<<1)) << (p+15));
        offs[t]=off;
        Tsm[w][i1][i0] = psi[base+off];
    }
    __syncwarp();
    // U[o][c] = sum_k C16[o][k] * T[k][c]   (applies C16 to column p+1 index)
    #pragma unroll
    for (int t=0;t<8;t++){
        int e = l + 32*t;
        int c = e & 15, o = e >> 4;
        float acc=0.f;
        #pragma unroll
        for (int k=0;k<16;k++) acc += Cs[o*16+k]*Tsm[w][k][c];
        Usm[w][o][c]=acc;
    }
    __syncwarp();
    // W[o][c'] = sum_c U[o][c] * C16[c'][c]  (applies C16 to column p index)
    #pragma unroll
    for (int t=0;t<8;t++){
        int e = l + 32*t;
        int i0 = e & 15, i1 = e >> 4;
        float acc=0.f;
        #pragma unroll
        for (int c=0;c<16;c++) acc += Cs[i0*16+c]*Usm[w][i1][c];
        psi[base+offs[t]] = acc;
    }
}

// ------------- single-column vertical (p=4), in-place -------------
__global__ __launch_bounds__(256) void v1_kernel(float* __restrict__ psi, int p){
    __shared__ float Cs[256];
    int tid=threadIdx.x;
    if (tid<256) Cs[tid]=g_C16[tid];
    __syncthreads();
    unsigned f = blockIdx.x*256u + (unsigned)tid;
    unsigned tt=f;
    tt = ((tt >> p)      << (p+1))  | (tt & ((1u<<p)-1u));
    tt = ((tt >> (p+5))  << (p+6))  | (tt & ((1u<<(p+5))-1u));
    tt = ((tt >> (p+10)) << (p+11)) | (tt & ((1u<<(p+10))-1u));
    tt = ((tt >> (p+15)) << (p+16)) | (tt & ((1u<<(p+15))-1u));
    unsigned base=tt;
    unsigned s0=1u<<p, s1=1u<<(p+5), s2=1u<<(p+10), s3=1u<<(p+15);
    float v[16];
    #pragma unroll
    for(int i=0;i<16;i++){
        unsigned a = base + (i&1)*s0 + ((i>>1)&1)*s1 + ((i>>2)&1)*s2 + ((i>>3)&1)*s3;
        v[i]=psi[a];
    }
    #pragma unroll 4
    for(int o=0;o<16;o++){
        float acc0=0.f, acc1=0.f;
        #pragma unroll
        for(int i=0;i<16;i+=2){
            acc0 += Cs[o*16+i]  *v[i];
            acc1 += Cs[o*16+i+1]*v[i+1];
        }
        unsigned a = base + (o&1)*s0 + ((o>>1)&1)*s1 + ((o>>2)&1)*s2 + ((o>>3)&1)*s3;
        psi[a]=acc0+acc1;
    }
}

// ------------- gather 64 amplitudes -------------
__global__ void gather_kernel(const int* __restrict__ x, const float* __restrict__ psi,
                              float* __restrict__ out){
    int b = threadIdx.x;
    unsigned idx=0;
    #pragma unroll
    for (int j=0;j<20;j++) idx = (idx<<1) | (unsigned)x[b*20+j];
    out[b]=psi[idx];
}

extern "C" void kernel_launch(void* const* d_in, const int* in_sizes, int n_in,
                              void* d_out, int out_size){
    const int*   x    = (const int*)d_in[0];
    const float* peps = (const float*)d_in[1];
    const float* gate = (const float*)d_in[2];
    float* out = (float*)d_out;

    float *A,*Cm,*psi;
    cudaGetSymbolAddress((void**)&A,    g_A);
    cudaGetSymbolAddress((void**)&Cm,   g_Cm);
    cudaGetSymbolAddress((void**)&psi,  g_psi);

    build_rc_kernel<<<1,1024>>>(gate);
    kprep_kernel<<<10,256>>>(peps);

    for (int j=0;j<5;j++){
        int twoJ2 = 2<<j;
        int fourJ2 = 4<<(2*j);
        int R = (j==4)?1:4;
        long nout = (long)twoJ2*twoJ2*fourJ2*R*R;
        int nb = (int)((nout+255)/256);
        afold_kernel<<<nb,256>>>(j);
    }
    for (int j=0;j<5;j++){
        int twoJ2 = 2<<j;
        int fourJ2 = 4<<(2*j);
        int R = (j==4)?1:4;
        long nout = (long)twoJ2*twoJ2*fourJ2*R*R;
        int nb = (int)((nout+255)/256);
        cfold_kernel<<<nb,256>>>(j);
    }

    sgemm_kernel<<<dim3(16,16),256>>>(A, Cm, psi);

    for (int sweep=0; sweep<5; sweep++){
        hhigh_kernel<<<128,256>>>(psi);   // bits [15-19] and [10-14]
        hlow_kernel<<<1024,256>>>(psi);   // bits [5-9] and [0-4]
        v2_kernel<<<512,256>>>(psi, 0);   // columns p=0,1
        v2_kernel<<<512,256>>>(psi, 2);   // columns p=2,3
        v1_kernel<<<256,256>>>(psi, 4);   // column  p=4
    }

    gather_kernel<<<1,64>>>(x, psi, out);
}

// round 4
// speedup vs baseline: 1.2774x; 1.0911x over previous
#include <cuda_runtime.h>

#define NS (1<<20)

// ---- device scratch (static, allocation-free) ----
__device__ float g_T0[NS];     // fold23 out, pair0
__device__ float g_T1[NS];     // fold23 out, pair1
__device__ float g_A[NS];      // T2 (pair*4096) early; then A[P01][bond] 1024x1024
__device__ float g_Cm[NS];     // C[bond][P23]  (1024x1024)
__device__ float g_psi[NS];    // statevector (in-place for sweeps)
__device__ float g_R[1024];    // 32x32 row-chain operator [out][in]
__device__ float g_C16[256];   // 16x16 column-chain operator
__device__ float g_K[10*4096]; // per-column pair tensors K_j
__device__ float g_KK[2*65536];// combined column-pair operators KK23 per pair

__device__ __forceinline__ float peps_el(const float* __restrict__ peps,
                                         int i,int j,int p,int u,int d,int l,int r){
    return peps[(((((i*5+j)*2+p)*4+u)*4+d)*4+l)*4+r];
}

// ------------- prep: blocks 0..9 compute K_j; block 10 builds R and C16 -------------
__global__ void prep_kernel(const float* __restrict__ peps, const float* __restrict__ gate){
    int t = threadIdx.x;  // 256
    if (blockIdx.x < 10){
        int blk = blockIdx.x;
        int pair = blk/5, j = blk%5;
        int L = (j==0)?1:4, R = (j==4)?1:4;
        int nk = 16*L*L*R*R;
        float* Kg = g_K + blk*4096;
        for (int e=t; e<nk; e+=256){
            int tt=e;
            int rb=tt%R; tt/=R; int ra=tt%R; tt/=R;
            int lb=tt%L; tt/=L; int la=tt%L; tt/=L;
            int mid=tt&3; tt>>=2;
            int pb=tt&1; int pa=tt>>1;
            float s=0.f;
            if (pair==0){
                #pragma unroll
                for(int m=0;m<4;m++)
                    s += peps_el(peps,0,j,pa,0,m,la,ra)*peps_el(peps,1,j,pb,m,mid,lb,rb);
            } else {
                #pragma unroll
                for(int m=0;m<4;m++)
                    s += peps_el(peps,2,j,pa,mid,m,la,ra)*peps_el(peps,3,j,pb,m,0,lb,rb);
            }
            Kg[e]=s;
        }
        return;
    }
    // ---- block 10: build R (32x32) and C16 (16x16) with 256 threads ----
    __shared__ float g[16];
    __shared__ float A0[1024];
    __shared__ float A1[1024];
    if (t<16) g[t]=gate[t];
    for (int e=t;e<1024;e+=256) A0[e] = ((e>>5)==(e&31)) ? 1.0f : 0.0f;
    __syncthreads();
    #pragma unroll
    for (int k=0;k<4;k++){
        const float* cur = (k&1)? A1 : A0;
        float* nxt       = (k&1)? A0 : A1;
        int hb=4-k, lb=3-k;
        for (int e=t;e<1024;e+=256){
            int rp=e>>5, c=e&31;
            int i1p=(rp>>hb)&1, i2p=(rp>>lb)&1;
            int base = rp & ~((1<<hb)|(1<<lb));
            float acc=0.f;
            #pragma unroll
            for(int i1=0;i1<2;i1++)
            #pragma unroll
            for(int i2=0;i2<2;i2++)
                acc += g[(i1p*2+i2p)*4+(i1*2+i2)] * cur[(base|(i1<<hb)|(i2<<lb))*32 + c];
            nxt[e]=acc;
        }
        __syncthreads();
    }
    for (int e=t;e<1024;e+=256) g_R[e]=A0[e];
    __syncthreads();
    if (t<256) A0[t] = ((t>>4)==(t&15)) ? 1.0f : 0.0f;
    __syncthreads();
    #pragma unroll
    for (int k=0;k<3;k++){
        const float* cur=(k&1)?A1:A0;
        float* nxt      =(k&1)?A0:A1;
        int hb=3-k, lb=2-k;
        int rp=t>>4, c=t&15;
        int i1p=(rp>>hb)&1,i2p=(rp>>lb)&1;
        int base = rp & ~((1<<hb)|(1<<lb));
        float acc=0.f;
        #pragma unroll
        for(int i1=0;i1<2;i1++)
        #pragma unroll
        for(int i2=0;i2<2;i2++)
            acc += g[(i1p*2+i2p)*4+(i1*2+i2)]*cur[(base|(i1<<hb)|(i2<<lb))*16+c];
        __syncthreads();
        nxt[t]=acc;
        __syncthreads();
    }
    g_C16[t]=A1[t];
}

// ------------- kkprep: blocks 0..255 build KK23 slices; block 256 builds T2 -------------
__global__ void kkprep_kernel(){
    int t = threadIdx.x;          // 256
    int pair = blockIdx.y;
    const float* Kbase = g_K + pair*5*4096;
    if (blockIdx.x < 256){
        int pb = blockIdx.x;
        int pd = pb&15, pbb = (pb>>4)&3, pa = pb>>6;
        int p0c2=pa>>1, p0c3=pa&1;
        int p1c2=pbb>>1, p1c3=pbb&1;
        int d1c2=pd>>2,  d1c3=pd&3;
        int kb2 = (p0c2*2+p1c2)*4+d1c2;
        int kb3 = (p0c3*2+p1c3)*4+d1c3;
        __shared__ float K2s[256], K3s[256];
        const float* K2 = Kbase + 2*4096;
        const float* K3 = Kbase + 3*4096;
        K2s[t] = K2[kb2*256 + t];   // [l][m]
        K3s[t] = K3[kb3*256 + t];   // [m][r]
        __syncthreads();
        int l = t>>4, r = t&15;
        float acc=0.f;
        #pragma unroll
        for (int m=0;m<16;m++) acc += K2s[l*16+m]*K3s[m*16+r];
        g_KK[pair*65536 + pb*256 + t] = acc;
        return;
    }
    // block 256: T2[abc(256)][r(16)] = sum_m K0[kb0][m] * K1[kb1][m][r]
    __shared__ float K0s[256];
    __shared__ float K1s[4096];
    const float* K0 = Kbase + 0*4096;
    const float* K1 = Kbase + 1*4096;
    K0s[t]=K0[t];
    for (int e=t;e<4096;e+=256) K1s[e]=K1[e];
    __syncthreads();
    int abc = t;
    int a2=abc>>6, b2=(abc>>4)&3, c2=abc&15;
    int kb0 = ((a2>>1)*2+(b2>>1))*4 + (c2>>2);
    int kb1 = ((a2&1)*2+(b2&1))*4 + (c2&3);
    float* T2 = g_A + pair*4096;
    #pragma unroll
    for (int r=0;r<16;r++){
        float acc=0.f;
        #pragma unroll
        for (int m=0;m<16;m++) acc += K0s[kb0*16+m]*K1s[(kb1*16+m)*16+r];
        T2[abc*16+r]=acc;
    }
}

// ------------- fold23: T4 = T2 x KK23 ; grid (256, 2) -------------
__global__ __launch_bounds__(256) void fold23_kernel(){
    int t = threadIdx.x;
    int pb = blockIdx.x, pair = blockIdx.y;
    int pd = pb&15, pbb = (pb>>4)&3, pa = pb>>6;
    __shared__ float Ts[256*20];    // T2 padded rows of 20
    __shared__ float Ks[256];       // KK23 slice [l][r]
    const float* T2 = g_A + pair*4096;
    for (int e=t;e<4096;e+=256){
        Ts[(e>>4)*20 + (e&15)] = T2[e];
    }
    Ks[t] = g_KK[pair*65536 + pb*256 + t];
    __syncthreads();
    float* Tout = pair? g_T1 : g_T0;
    int a2=t>>6, b2=(t>>4)&3, c2=t&15;
    float tv[16];
    #pragma unroll
    for (int l=0;l<16;l++) tv[l]=Ts[t*20+l];
    long obase = ((((long)(a2*4+pa)*16 + b2*4+pbb)*256) + c2*16+pd)*16;
    #pragma unroll
    for (int r4=0;r4<4;r4++){
        float4 o;
        float* po=(float*)&o;
        #pragma unroll
        for (int q=0;q<4;q++){
            int r=r4*4+q;
            float acc=0.f;
            #pragma unroll
            for (int l=0;l<16;l++) acc += tv[l]*Ks[l*16+r];
            po[q]=acc;
        }
        *(float4*)&Tout[obase + r4*4] = o;
    }
}

// ------------- fold4: final column -> A / C ; grid (16, 2) -------------
__global__ __launch_bounds__(256) void fold4_kernel(){
    int t = threadIdx.x;
    int a = blockIdx.x, pair = blockIdx.y;
    __shared__ float K4s[256];
    K4s[t] = g_K[(pair*5+4)*4096 + t];   // [kb(16)][l(16)]
    __syncthreads();
    const float* Tin = pair? g_T1 : g_T0;
    float* Aout = g_A; float* Cout = g_Cm;
    for (int i=0;i<16;i++){
        int b=i, c=t;
        const float* tp = &Tin[(((long)(a*16+b)*256)+c)*16];
        float tv[16];
        #pragma unroll
        for (int l4=0;l4<4;l4++){
            float4 v = *(const float4*)&tp[l4*4];
            tv[l4*4+0]=v.x; tv[l4*4+1]=v.y; tv[l4*4+2]=v.z; tv[l4*4+3]=v.w;
        }
        if (pair==0){
            long base = (long)a*65536 + (long)b*2048 + c*4;
            #pragma unroll
            for (int p0=0;p0<2;p0++)
            #pragma unroll
            for (int p1=0;p1<2;p1++){
                float4 o; float* po=(float*)&o;
                #pragma unroll
                for (int d1=0;d1<4;d1++){
                    int kb=(p0*2+p1)*4+d1;
                    float acc=0.f;
                    #pragma unroll
                    for (int l=0;l<16;l++) acc += tv[l]*K4s[kb*16+l];
                    po[d1]=acc;
                }
                *(float4*)&Aout[base + p0*32768 + p1*1024] = o;
            }
        } else {
            #pragma unroll
            for (int p0=0;p0<2;p0++)
            #pragma unroll
            for (int p1=0;p1<2;p1++)
            #pragma unroll
            for (int d1=0;d1<4;d1++){
                int kb=(p0*2+p1)*4+d1;
                float acc=0.f;
                #pragma unroll
                for (int l=0;l<16;l++) acc += tv[l]*K4s[kb*16+l];
                Cout[(long)(c*4+d1)*1024 + (a*2+p0)*32 + b*2+p1] = acc;
            }
        }
    }
}

// ------------- psi = A(1024x1024) @ C(1024x1024) -------------
__global__ __launch_bounds__(256) void sgemm_kernel(const float* __restrict__ A,
        const float* __restrict__ B, float* __restrict__ Cout){
    __shared__ float As[16][68];
    __shared__ float Bs[16][64];
    int bx=blockIdx.x, by=blockIdx.y;
    int tid=threadIdx.x;
    int tx=tid&15, ty=tid>>4;
    float acc[4][4];
    #pragma unroll
    for(int i=0;i<4;i++)
      #pragma unroll
      for(int jj=0;jj<4;jj++) acc[i][jj]=0.f;

    const float* Ablk = A + (long)(by*64)*1024;
    const float* Bblk = B + bx*64;
    for (int k0=0;k0<1024;k0+=16){
        #pragma unroll
        for (int e=0;e<4;e++){
            int idx = tid + e*256;
            int m = idx>>4, k = idx&15;
            As[k][m] = Ablk[(long)m*1024 + k0 + k];
        }
        #pragma unroll
        for (int e=0;e<4;e++){
            int idx = tid + e*256;
            int k = idx>>6, n = idx&63;
            Bs[k][n] = Bblk[(long)(k0+k)*1024 + n];
        }
        __syncthreads();
        #pragma unroll
        for (int k=0;k<16;k++){
            float4 a4 = *(const float4*)&As[k][ty*4];
            float4 b4 = *(const float4*)&Bs[k][tx*4];
            acc[0][0]+=a4.x*b4.x; acc[0][1]+=a4.x*b4.y; acc[0][2]+=a4.x*b4.z; acc[0][3]+=a4.x*b4.w;
            acc[1][0]+=a4.y*b4.x; acc[1][1]+=a4.y*b4.y; acc[1][2]+=a4.y*b4.z; acc[1][3]+=a4.y*b4.w;
            acc[2][0]+=a4.z*b4.x; acc[2][1]+=a4.z*b4.y; acc[2][2]+=a4.z*b4.z; acc[2][3]+=a4.z*b4.w;
            acc[3][0]+=a4.w*b4.x; acc[3][1]+=a4.w*b4.y; acc[3][2]+=a4.w*b4.z; acc[3][3]+=a4.w*b4.w;
        }
        __syncthreads();
    }
    #pragma unroll
    for(int i=0;i<4;i++){
        float4 o = make_float4(acc[i][0],acc[i][1],acc[i][2],acc[i][3]);
        *(float4*)&Cout[(long)(by*64+ty*4+i)*1024 + bx*64+tx*4] = o;
    }
}

// ------------- fused horizontal low: bits [5-9] and [0-4], in-place -------------
__global__ __launch_bounds__(256) void hlow_kernel(float* __restrict__ psi){
    __shared__ float T[32][33];
    __shared__ float Usm[32][33];
    __shared__ float Rs[1024];
    __shared__ float RsT[1024];
    int tid=threadIdx.x;
    for (int e=tid;e<1024;e+=256){
        float v = g_R[e];
        Rs[e]=v;
        RsT[(e&31)*32 + (e>>5)] = v;
    }
    unsigned base = blockIdx.x*1024u;
    #pragma unroll
    for (int it=0;it<4;it++){
        int e = tid + it*256;
        T[e>>5][e&31] = psi[base+e];
    }
    __syncthreads();
    int rp = tid & 31, cq = tid >> 5;
    float u[4]={0.f,0.f,0.f,0.f};
    for (int r=0;r<32;r++){
        float rv = RsT[r*32+rp];
        #pragma unroll
        for (int i=0;i<4;i++) u[i] += rv * T[r][cq*4+i];
    }
    #pragma unroll
    for (int i=0;i<4;i++) Usm[rp][cq*4+i]=u[i];
    __syncthreads();
    float w[4];
    #pragma unroll
    for (int i=0;i<4;i++){
        int cp = cq*4+i;
        float acc=0.f;
        #pragma unroll
        for (int c=0;c<32;c++) acc += Rs[cp*32+c]*Usm[rp][c];
        w[i]=acc;
    }
    __syncthreads();
    #pragma unroll
    for (int i=0;i<4;i++) T[rp][cq*4+i]=w[i];
    __syncthreads();
    #pragma unroll
    for (int it=0;it<4;it++){
        int e = tid + it*256;
        psi[base+e] = T[e>>5][e&31];
    }
}

// ------------- fused horizontal high: bits [15-19] and [10-14], in-place -------------
__global__ __launch_bounds__(256) void hhigh_kernel(float* __restrict__ psi){
    __shared__ float S[8][1036];
    __shared__ float Rs[1024];
    __shared__ float RsT[1024];
    int tid = threadIdx.x;
    for (int e=tid;e<1024;e+=256){
        float v = g_R[e];
        Rs[e]=v;
        RsT[(e&31)*32 + (e>>5)] = v;
    }
    unsigned lowbase = blockIdx.x * 8u;
    for (int it=0; it<32; it++){
        int idx = tid + it*256;
        int lo = idx & 7, k = idx >> 3;
        S[lo][k] = psi[(unsigned)k*1024u + lowbase + (unsigned)lo];
    }
    __syncthreads();
    int low = tid & 7, rp = tid >> 3;
    float U[32];
    #pragma unroll
    for (int c=0;c<32;c++) U[c]=0.f;
    for (int r=0;r<32;r++){
        float rv = RsT[r*32+rp];
        const float4* row = (const float4*)&S[low][r*32];
        #pragma unroll
        for (int c4=0;c4<8;c4++){
            float4 t = row[c4];
            U[c4*4+0] += rv*t.x; U[c4*4+1] += rv*t.y;
            U[c4*4+2] += rv*t.z; U[c4*4+3] += rv*t.w;
        }
    }
    float W[32];
    #pragma unroll
    for (int cp=0;cp<32;cp++){
        float acc=0.f;
        #pragma unroll
        for (int c=0;c<32;c++) acc += Rs[cp*32+c]*U[c];
        W[cp]=acc;
    }
    __syncthreads();
    #pragma unroll
    for (int cp=0;cp<32;cp++) S[low][rp*32+cp] = W[cp];
    __syncthreads();
    for (int it=0; it<32; it++){
        int idx = tid + it*256;
        int lo = idx & 7, k = idx >> 3;
        psi[(unsigned)k*1024u + lowbase + (unsigned)lo] = S[lo][k];
    }
}

// ------------- v2: columns p and p+1 (used with p=0), in-place -------------
__global__ __launch_bounds__(256) void v2_kernel(float* __restrict__ psi, int p){
    __shared__ float Cs[256];
    __shared__ float Tsm[8][16][17];
    __shared__ float Usm[8][16][17];
    int tid=threadIdx.x;
    if (tid<256) Cs[tid]=g_C16[tid];
    int w = tid>>5, l = tid&31;
    unsigned f = blockIdx.x*8u + (unsigned)w;
    unsigned tt=f;
    tt = ((tt>>p)<<(p+2))        | (tt & ((1u<<p)-1u));
    tt = ((tt>>(p+5))<<(p+7))    | (tt & ((1u<<(p+5))-1u));
    tt = ((tt>>(p+10))<<(p+12))  | (tt & ((1u<<(p+10))-1u));
    tt = ((tt>>(p+15))<<(p+17))  | (tt & ((1u<<(p+15))-1u));
    unsigned base=tt;
    __syncthreads();
    unsigned offs[8];
    #pragma unroll
    for (int t=0;t<8;t++){
        int e = l + 32*t;
        int i0 = e & 15, i1 = e >> 4;
        unsigned off =
            (unsigned)(((i0&1)|((i1&1)<<1)) << p) |
            (unsigned)((((i0>>1)&1)|(((i1>>1)&1)<<1)) << (p+5)) |
            (unsigned)((((i0>>2)&1)|(((i1>>2)&1)<<1)) << (p+10)) |
            (unsigned)((((i0>>3)&1)|(((i1>>3)&1)<<1)) << (p+15));
        offs[t]=off;
        Tsm[w][i1][i0] = psi[base+off];
    }
    __syncwarp();
    #pragma unroll
    for (int t=0;t<8;t++){
        int e = l + 32*t;
        int c = e & 15, o = e >> 4;
        float acc=0.f;
        #pragma unroll
        for (int k=0;k<16;k++) acc += Cs[o*16+k]*Tsm[w][k][c];
        Usm[w][o][c]=acc;
    }
    __syncwarp();
    #pragma unroll
    for (int t=0;t<8;t++){
        int e = l + 32*t;
        int i0 = e & 15, i1 = e >> 4;
        float acc=0.f;
        #pragma unroll
        for (int c=0;c<16;c++) acc += Cs[i0*16+c]*Usm[w][i1][c];
        psi[base+offs[t]] = acc;
    }
}

// ------------- v3: columns p=2,3,4 in one pass, in-place -------------
// fiber = 12 bits {2,7,12,17 | 3,8,13,18 | 4,9,14,19}; complement 8 bits -> blockIdx
__global__ __launch_bounds__(256) void v3_kernel(float* __restrict__ psi){
    __shared__ float Cs[256];
    __shared__ float S[256*17 + 16];
    int t=threadIdx.x;
    Cs[t]=g_C16[t];
    unsigned f = blockIdx.x;  // 8 bits
    unsigned tt=f;
    tt = ((tt>>2)<<5)   | (tt & 3u);
    tt = ((tt>>7)<<10)  | (tt & 127u);
    tt = ((tt>>12)<<15) | (tt & 4095u);
    tt = ((tt>>17)<<20) | (tt & 131071u);
    unsigned base=tt;
    // element (a,b,c): a at bits {2,7,12,17}, b at +1, c at +2
    // load: thread t = (b,c); smem layout S[(b*16+c)*17 + a]
    {
        int b=t>>4, c=t&15;
        unsigned offb = ((unsigned)(b&1)<<3)|((unsigned)((b>>1)&1)<<8)|((unsigned)((b>>2)&1)<<13)|((unsigned)((b>>3)&1)<<18);
        unsigned offc = ((unsigned)(c&1)<<4)|((unsigned)((c>>1)&1)<<9)|((unsigned)((c>>2)&1)<<14)|((unsigned)((c>>3)&1)<<19);
        unsigned bs = base + offb + offc;
        #pragma unroll
        for (int a=0;a<16;a++){
            unsigned offa = ((unsigned)(a&1)<<2)|((unsigned)((a>>1)&1)<<7)|((unsigned)((a>>2)&1)<<12)|((unsigned)((a>>3)&1)<<17);
            S[t*17 + a] = psi[bs + offa];
        }
    }
    __syncthreads();
    // stage A: transform a; thread owns row (b,c)
    {
        float v[16], o[16];
        #pragma unroll
        for (int a=0;a<16;a++) v[a]=S[t*17+a];
        #pragma unroll
        for (int ap=0;ap<16;ap++){
            float acc=0.f;
            #pragma unroll
            for (int a=0;a<16;a++) acc += Cs[ap*16+a]*v[a];
            o[ap]=acc;
        }
        #pragma unroll
        for (int a=0;a<16;a++) S[t*17+a]=o[a];
    }
    __syncthreads();
    // stage B: transform b; thread = (a fast? a = t>>4, c = t&15)
    {
        int a=t>>4, c=t&15;
        float v[16], o[16];
        #pragma unroll
        for (int b=0;b<16;b++) v[b]=S[(b*16+c)*17 + a];
        #pragma unroll
        for (int bp=0;bp<16;bp++){
            float acc=0.f;
            #pragma unroll
            for (int b=0;b<16;b++) acc += Cs[bp*16+b]*v[b];
            o[bp]=acc;
        }
        #pragma unroll
        for (int b=0;b<16;b++) S[(b*16+c)*17 + a]=o[b];
    }
    __syncthreads();
    // stage C: transform c; thread = (a = t&15, b = t>>4)
    {
        int a=t&15, b=t>>4;
        float v[16], o[16];
        #pragma unroll
        for (int c=0;c<16;c++) v[c]=S[(b*16+c)*17 + a];
        #pragma unroll
        for (int cp=0;cp<16;cp++){
            float acc=0.f;
            #pragma unroll
            for (int c=0;c<16;c++) acc += Cs[cp*16+c]*v[c];
            o[cp]=acc;
        }
        #pragma unroll
        for (int c=0;c<16;c++) S[(b*16+c)*17 + a]=o[c];
    }
    __syncthreads();
    // store: thread t = (b,c) writes its row
    {
        int b=t>>4, c=t&15;
        unsigned offb = ((unsigned)(b&1)<<3)|((unsigned)((b>>1)&1)<<8)|((unsigned)((b>>2)&1)<<13)|((unsigned)((b>>3)&1)<<18);
        unsigned offc = ((unsigned)(c&1)<<4)|((unsigned)((c>>1)&1)<<9)|((unsigned)((c>>2)&1)<<14)|((unsigned)((c>>3)&1)<<19);
        unsigned bs = base + offb + offc;
        #pragma unroll
        for (int a=0;a<16;a++){
            unsigned offa = ((unsigned)(a&1)<<2)|((unsigned)((a>>1)&1)<<7)|((unsigned)((a>>2)&1)<<12)|((unsigned)((a>>3)&1)<<17);
            psi[bs + offa] = S[t*17 + a];
        }
    }
}

// ------------- gather 64 amplitudes -------------
__global__ void gather_kernel(const int* __restrict__ x, const float* __restrict__ psi,
                              float* __restrict__ out){
    int b = threadIdx.x;
    unsigned idx=0;
    #pragma unroll
    for (int j=0;j<20;j++) idx = (idx<<1) | (unsigned)x[b*20+j];
    out[b]=psi[idx];
}

extern "C" void kernel_launch(void* const* d_in, const int* in_sizes, int n_in,
                              void* d_out, int out_size){
    const int*   x    = (const int*)d_in[0];
    const float* peps = (const float*)d_in[1];
    const float* gate = (const float*)d_in[2];
    float* out = (float*)d_out;

    float *A,*Cm,*psi;
    cudaGetSymbolAddress((void**)&A,    g_A);
    cudaGetSymbolAddress((void**)&Cm,   g_Cm);
    cudaGetSymbolAddress((void**)&psi,  g_psi);

    prep_kernel<<<11,256>>>(peps, gate);
    kkprep_kernel<<<dim3(257,2),256>>>();
    fold23_kernel<<<dim3(256,2),256>>>();
    fold4_kernel<<<dim3(16,2),256>>>();

    sgemm_kernel<<<dim3(16,16),256>>>(A, Cm, psi);

    for (int sweep=0; sweep<5; sweep++){
        hhigh_kernel<<<128,256>>>(psi);   // bits [15-19] and [10-14]
        hlow_kernel<<<1024,256>>>(psi);   // bits [5-9] and [0-4]
        v3_kernel<<<256,256>>>(psi);      // columns at p=2,3,4
        v2_kernel<<<512,256>>>(psi, 0);   // columns at p=0,1
    }

    gather_kernel<<<1,64>>>(x, psi, out);
}

// round 5
// speedup vs baseline: 1.3886x; 1.0870x over previous
#include <cuda_runtime.h>

#define NS (1<<20)

// ---- device scratch (static, allocation-free) ----
__device__ float g_T0[NS];     // fold23 out, pair0
__device__ float g_T1[NS];     // fold23 out, pair1
__device__ float g_A[NS];      // T2 (pair*4096) early; then A[P01][bond] 1024x1024
__device__ float g_Cm[NS];     // Ct[P23][bond]  (1024x1024, transposed C)
__device__ float g_psi[NS];    // statevector (in-place for sweeps)
__device__ float g_R[1024];    // 32x32 row-chain operator [out][in]
__device__ float g_C16[256];   // 16x16 column-chain operator
__device__ float g_K[10*4096]; // per-column pair tensors K_j
__device__ float g_KK[2*65536];// combined column-pair operators KK23 per pair

// ---- packed fp32x2 helpers ----
__device__ __forceinline__ unsigned long long pk2(float x, float y){
    unsigned long long r; asm("mov.b64 %0,{%1,%2};" : "=l"(r) : "f"(x), "f"(y)); return r;
}
__device__ __forceinline__ float2 upk2(unsigned long long v){
    float2 r; asm("mov.b64 {%0,%1},%2;" : "=f"(r.x), "=f"(r.y) : "l"(v)); return r;
}
__device__ __forceinline__ unsigned long long fma2(unsigned long long a,
        unsigned long long b, unsigned long long c){
    unsigned long long d;
    asm("fma.rn.f32x2 %0,%1,%2,%3;" : "=l"(d) : "l"(a), "l"(b), "l"(c));
    return d;
}

__device__ __forceinline__ float peps_el(const float* __restrict__ peps,
                                         int i,int j,int p,int u,int d,int l,int r){
    return peps[(((((i*5+j)*2+p)*4+u)*4+d)*4+l)*4+r];
}

// ------------- prep: blocks 0..9 compute K_j; block 10 builds R and C16 -------------
__global__ void prep_kernel(const float* __restrict__ peps, const float* __restrict__ gate){
    int t = threadIdx.x;  // 256
    if (blockIdx.x < 10){
        int blk = blockIdx.x;
        int pair = blk/5, j = blk%5;
        int L = (j==0)?1:4, R = (j==4)?1:4;
        int nk = 16*L*L*R*R;
        float* Kg = g_K + blk*4096;
        for (int e=t; e<nk; e+=256){
            int tt=e;
            int rb=tt%R; tt/=R; int ra=tt%R; tt/=R;
            int lb=tt%L; tt/=L; int la=tt%L; tt/=L;
            int mid=tt&3; tt>>=2;
            int pb=tt&1; int pa=tt>>1;
            float s=0.f;
            if (pair==0){
                #pragma unroll
                for(int m=0;m<4;m++)
                    s += peps_el(peps,0,j,pa,0,m,la,ra)*peps_el(peps,1,j,pb,m,mid,lb,rb);
            } else {
                #pragma unroll
                for(int m=0;m<4;m++)
                    s += peps_el(peps,2,j,pa,mid,m,la,ra)*peps_el(peps,3,j,pb,m,0,lb,rb);
            }
            Kg[e]=s;
        }
        return;
    }
    // ---- block 10: build R (32x32) and C16 (16x16) with 256 threads ----
    __shared__ float g[16];
    __shared__ float A0[1024];
    __shared__ float A1[1024];
    if (t<16) g[t]=gate[t];
    for (int e=t;e<1024;e+=256) A0[e] = ((e>>5)==(e&31)) ? 1.0f : 0.0f;
    __syncthreads();
    #pragma unroll
    for (int k=0;k<4;k++){
        const float* cur = (k&1)? A1 : A0;
        float* nxt       = (k&1)? A0 : A1;
        int hb=4-k, lb=3-k;
        for (int e=t;e<1024;e+=256){
            int rp=e>>5, c=e&31;
            int i1p=(rp>>hb)&1, i2p=(rp>>lb)&1;
            int base = rp & ~((1<<hb)|(1<<lb));
            float acc=0.f;
            #pragma unroll
            for(int i1=0;i1<2;i1++)
            #pragma unroll
            for(int i2=0;i2<2;i2++)
                acc += g[(i1p*2+i2p)*4+(i1*2+i2)] * cur[(base|(i1<<hb)|(i2<<lb))*32 + c];
            nxt[e]=acc;
        }
        __syncthreads();
    }
    for (int e=t;e<1024;e+=256) g_R[e]=A0[e];
    __syncthreads();
    if (t<256) A0[t] = ((t>>4)==(t&15)) ? 1.0f : 0.0f;
    __syncthreads();
    #pragma unroll
    for (int k=0;k<3;k++){
        const float* cur=(k&1)?A1:A0;
        float* nxt      =(k&1)?A0:A1;
        int hb=3-k, lb=2-k;
        int rp=t>>4, c=t&15;
        int i1p=(rp>>hb)&1,i2p=(rp>>lb)&1;
        int base = rp & ~((1<<hb)|(1<<lb));
        float acc=0.f;
        #pragma unroll
        for(int i1=0;i1<2;i1++)
        #pragma unroll
        for(int i2=0;i2<2;i2++)
            acc += g[(i1p*2+i2p)*4+(i1*2+i2)]*cur[(base|(i1<<hb)|(i2<<lb))*16+c];
        __syncthreads();
        nxt[t]=acc;
        __syncthreads();
    }
    g_C16[t]=A1[t];
}

// ------------- kkprep: blocks 0..255 build KK23 slices; block 256 builds T2 -------------
__global__ void kkprep_kernel(){
    int t = threadIdx.x;          // 256
    int pair = blockIdx.y;
    const float* Kbase = g_K + pair*5*4096;
    if (blockIdx.x < 256){
        int pb = blockIdx.x;
        int pd = pb&15, pbb = (pb>>4)&3, pa = pb>>6;
        int p0c2=pa>>1, p0c3=pa&1;
        int p1c2=pbb>>1, p1c3=pbb&1;
        int d1c2=pd>>2,  d1c3=pd&3;
        int kb2 = (p0c2*2+p1c2)*4+d1c2;
        int kb3 = (p0c3*2+p1c3)*4+d1c3;
        __shared__ float K2s[256], K3s[256];
        const float* K2 = Kbase + 2*4096;
        const float* K3 = Kbase + 3*4096;
        K2s[t] = K2[kb2*256 + t];   // [l][m]
        K3s[t] = K3[kb3*256 + t];   // [m][r]
        __syncthreads();
        int l = t>>4, r = t&15;
        float acc=0.f;
        #pragma unroll
        for (int m=0;m<16;m++) acc += K2s[l*16+m]*K3s[m*16+r];
        g_KK[pair*65536 + pb*256 + t] = acc;
        return;
    }
    // block 256: T2[abc(256)][r(16)] = sum_m K0[kb0][m] * K1[kb1][m][r]
    __shared__ float K0s[256];
    __shared__ float K1s[4096];
    const float* K0 = Kbase + 0*4096;
    const float* K1 = Kbase + 1*4096;
    K0s[t]=K0[t];
    for (int e=t;e<4096;e+=256) K1s[e]=K1[e];
    __syncthreads();
    int abc = t;
    int a2=abc>>6, b2=(abc>>4)&3, c2=abc&15;
    int kb0 = ((a2>>1)*2+(b2>>1))*4 + (c2>>2);
    int kb1 = ((a2&1)*2+(b2&1))*4 + (c2&3);
    float* T2 = g_A + pair*4096;
    #pragma unroll
    for (int r=0;r<16;r++){
        float acc=0.f;
        #pragma unroll
        for (int m=0;m<16;m++) acc += K0s[kb0*16+m]*K1s[(kb1*16+m)*16+r];
        T2[abc*16+r]=acc;
    }
}

// ------------- fold23: T4 = T2 x KK23 ; grid (256, 2) -------------
__global__ __launch_bounds__(256) void fold23_kernel(){
    int t = threadIdx.x;
    int pb = blockIdx.x, pair = blockIdx.y;
    int pd = pb&15, pbb = (pb>>4)&3, pa = pb>>6;
    __shared__ float Ts[256*20];    // T2 padded rows of 20
    __shared__ float Ks[256];       // KK23 slice [l][r]
    const float* T2 = g_A + pair*4096;
    for (int e=t;e<4096;e+=256){
        Ts[(e>>4)*20 + (e&15)] = T2[e];
    }
    Ks[t] = g_KK[pair*65536 + pb*256 + t];
    __syncthreads();
    float* Tout = pair? g_T1 : g_T0;
    int a2=t>>6, b2=(t>>4)&3, c2=t&15;
    float tv[16];
    #pragma unroll
    for (int l=0;l<16;l++) tv[l]=Ts[t*20+l];
    long obase = ((((long)(a2*4+pa)*16 + b2*4+pbb)*256) + c2*16+pd)*16;
    #pragma unroll
    for (int r4=0;r4<4;r4++){
        float4 o;
        float* po=(float*)&o;
        #pragma unroll
        for (int q=0;q<4;q++){
            int r=r4*4+q;
            float acc=0.f;
            #pragma unroll
            for (int l=0;l<16;l++) acc += tv[l]*Ks[l*16+r];
            po[q]=acc;
        }
        *(float4*)&Tout[obase + r4*4] = o;
    }
}

// ------------- fold4: final column -> A / Ct ; grid (256, 2), thread = c -------------
__global__ __launch_bounds__(256) void fold4_kernel(){
    int c = threadIdx.x;
    int a = blockIdx.x >> 4, b = blockIdx.x & 15;
    int pair = blockIdx.y;
    __shared__ float K4s[256];
    K4s[c] = g_K[(pair*5+4)*4096 + c];   // [kb(16)][l(16)]
    __syncthreads();
    const float* Tin = pair? g_T1 : g_T0;
    const float* tp = &Tin[(((long)(a*16+b)*256)+c)*16];
    float tv[16];
    #pragma unroll
    for (int l4=0;l4<4;l4++){
        float4 v = *(const float4*)&tp[l4*4];
        tv[l4*4+0]=v.x; tv[l4*4+1]=v.y; tv[l4*4+2]=v.z; tv[l4*4+3]=v.w;
    }
    if (pair==0){
        long base = (long)a*65536 + (long)b*2048 + c*4;
        #pragma unroll
        for (int p0=0;p0<2;p0++)
        #pragma unroll
        for (int p1=0;p1<2;p1++){
            float4 o; float* po=(float*)&o;
            #pragma unroll
            for (int d1=0;d1<4;d1++){
                int kb=(p0*2+p1)*4+d1;
                float acc=0.f;
                #pragma unroll
                for (int l=0;l<16;l++) acc += tv[l]*K4s[kb*16+l];
                po[d1]=acc;
            }
            *(float4*)&g_A[base + p0*32768 + p1*1024] = o;
        }
    } else {
        // Ct[col][bond]: col = a*64+p0*32+b*2+p1, bond = c*4+d1 (coalesced over c)
        #pragma unroll
        for (int p0=0;p0<2;p0++)
        #pragma unroll
        for (int p1=0;p1<2;p1++){
            float4 o; float* po=(float*)&o;
            #pragma unroll
            for (int d1=0;d1<4;d1++){
                int kb=(p0*2+p1)*4+d1;
                float acc=0.f;
                #pragma unroll
                for (int l=0;l<16;l++) acc += tv[l]*K4s[kb*16+l];
                po[d1]=acc;
            }
            long col = (long)(a*64 + p0*32 + b*2 + p1);
            *(float4*)&g_Cm[col*1024 + c*4] = o;
        }
    }
}

// ------------- psi = A(1024x1024) @ Ct^T : packed f32x2 FFMA -------------
__global__ __launch_bounds__(256) void sgemm_kernel(const float* __restrict__ A,
        const float* __restrict__ Bt, float* __restrict__ Cout){
    __shared__ __align__(16) float As2[16][132];  // duplicated (a,a) pairs
    __shared__ __align__(16) float Bs[16][68];
    int bx=blockIdx.x, by=blockIdx.y;
    int tid=threadIdx.x;
    int tx=tid&15, ty=tid>>4;
    unsigned long long acc2[4][2];
    #pragma unroll
    for(int i=0;i<4;i++){ acc2[i][0]=0ull; acc2[i][1]=0ull; }

    const float* Ablk = A + (long)(by*64)*1024;
    const float* Btblk = Bt + (long)(bx*64)*1024;
    for (int k0=0;k0<1024;k0+=16){
        #pragma unroll
        for (int e=0;e<4;e++){
            int idx = tid + e*256;
            int m = idx>>4, k = idx&15;
            float v = Ablk[(long)m*1024 + k0 + k];
            *(float2*)&As2[k][2*m] = make_float2(v,v);
        }
        #pragma unroll
        for (int e=0;e<4;e++){
            int idx = tid + e*256;
            int n = idx>>4, k = idx&15;
            Bs[k][n] = Btblk[(long)n*1024 + k0 + k];
        }
        __syncthreads();
        #pragma unroll
        for (int k=0;k<16;k++){
            ulonglong2 a01 = *(const ulonglong2*)&As2[k][ty*8];
            ulonglong2 a23 = *(const ulonglong2*)&As2[k][ty*8+4];
            ulonglong2 bb  = *(const ulonglong2*)&Bs[k][tx*4];
            acc2[0][0]=fma2(a01.x, bb.x, acc2[0][0]); acc2[0][1]=fma2(a01.x, bb.y, acc2[0][1]);
            acc2[1][0]=fma2(a01.y, bb.x, acc2[1][0]); acc2[1][1]=fma2(a01.y, bb.y, acc2[1][1]);
            acc2[2][0]=fma2(a23.x, bb.x, acc2[2][0]); acc2[2][1]=fma2(a23.x, bb.y, acc2[2][1]);
            acc2[3][0]=fma2(a23.y, bb.x, acc2[3][0]); acc2[3][1]=fma2(a23.y, bb.y, acc2[3][1]);
        }
        __syncthreads();
    }
    #pragma unroll
    for(int i=0;i<4;i++){
        float2 c0 = upk2(acc2[i][0]);
        float2 c1 = upk2(acc2[i][1]);
        float4 o = make_float4(c0.x, c0.y, c1.x, c1.y);
        *(float4*)&Cout[(long)(by*64+ty*4+i)*1024 + bx*64+tx*4] = o;
    }
}

// ------------- fused horizontal low: bits [5-9] and [0-4], in-place -------------
__global__ __launch_bounds__(256) void hlow_kernel(float* __restrict__ psi){
    __shared__ float T[32][33];
    __shared__ float Usm[32][33];
    __shared__ float Rs[1024];
    __shared__ float RsT[1024];
    int tid=threadIdx.x;
    for (int e=tid;e<1024;e+=256){
        float v = g_R[e];
        Rs[e]=v;
        RsT[(e&31)*32 + (e>>5)] = v;
    }
    unsigned base = blockIdx.x*1024u;
    #pragma unroll
    for (int it=0;it<4;it++){
        int e = tid + it*256;
        T[e>>5][e&31] = psi[base+e];
    }
    __syncthreads();
    int rp = tid & 31, cq = tid >> 5;
    float u[4]={0.f,0.f,0.f,0.f};
    for (int r=0;r<32;r++){
        float rv = RsT[r*32+rp];
        #pragma unroll
        for (int i=0;i<4;i++) u[i] += rv * T[r][cq*4+i];
    }
    #pragma unroll
    for (int i=0;i<4;i++) Usm[rp][cq*4+i]=u[i];
    __syncthreads();
    float w[4];
    #pragma unroll
    for (int i=0;i<4;i++){
        int cp = cq*4+i;
        float acc=0.f;
        #pragma unroll
        for (int c=0;c<32;c++) acc += Rs[cp*32+c]*Usm[rp][c];
        w[i]=acc;
    }
    __syncthreads();
    #pragma unroll
    for (int i=0;i<4;i++) T[rp][cq*4+i]=w[i];
    __syncthreads();
    #pragma unroll
    for (int it=0;it<4;it++){
        int e = tid + it*256;
        psi[base+e] = T[e>>5][e&31];
    }
}

// ------------- fused horizontal high: bits [15-19] and [10-14], packed f32x2 -------------
__global__ __launch_bounds__(256) void hhigh_kernel(float* __restrict__ psi){
    __shared__ __align__(16) float S[8][1036];
    __shared__ __align__(16) float Rs[1024];
    __shared__ float RsT[1024];
    int tid = threadIdx.x;
    for (int e=tid;e<1024;e+=256){
        float v = g_R[e];
        Rs[e]=v;
        RsT[(e&31)*32 + (e>>5)] = v;
    }
    unsigned lowbase = blockIdx.x * 8u;
    for (int it=0; it<32; it++){
        int idx = tid + it*256;
        int lo = idx & 7, k = idx >> 3;
        S[lo][k] = psi[(unsigned)k*1024u + lowbase + (unsigned)lo];
    }
    __syncthreads();
    int low = tid & 7, rp = tid >> 3;
    unsigned long long U2[16];
    #pragma unroll
    for (int e=0;e<16;e++) U2[e]=0ull;
    for (int r=0;r<32;r++){
        float rv = RsT[r*32+rp];
        unsigned long long rvp = pk2(rv, rv);
        const ulonglong2* row2 = (const ulonglong2*)&S[low][r*32];
        #pragma unroll
        for (int c2=0;c2<8;c2++){
            ulonglong2 tp = row2[c2];
            U2[c2*2+0] = fma2(rvp, tp.x, U2[c2*2+0]);
            U2[c2*2+1] = fma2(rvp, tp.y, U2[c2*2+1]);
        }
    }
    float W[32];
    #pragma unroll
    for (int cp=0;cp<32;cp++){
        const ulonglong2* Rp2 = (const ulonglong2*)&Rs[cp*32];
        unsigned long long s2 = 0ull;
        #pragma unroll
        for (int c2=0;c2<8;c2++){
            ulonglong2 rr = Rp2[c2];
            s2 = fma2(rr.x, U2[c2*2+0], s2);
            s2 = fma2(rr.y, U2[c2*2+1], s2);
        }
        float2 f = upk2(s2);
        W[cp] = f.x + f.y;
    }
    __syncthreads();
    #pragma unroll
    for (int cp=0;cp<32;cp++) S[low][rp*32+cp] = W[cp];
    __syncthreads();
    for (int it=0; it<32; it++){
        int idx = tid + it*256;
        int lo = idx & 7, k = idx >> 3;
        psi[(unsigned)k*1024u + lowbase + (unsigned)lo] = S[lo][k];
    }
}

// ------------- v2: columns p and p+1 (used with p=0), in-place -------------
__global__ __launch_bounds__(256) void v2_kernel(float* __restrict__ psi, int p){
    __shared__ float Cs[256];
    __shared__ float Tsm[8][16][17];
    __shared__ float Usm[8][16][17];
    int tid=threadIdx.x;
    if (tid<256) Cs[tid]=g_C16[tid];
    int w = tid>>5, l = tid&31;
    unsigned f = blockIdx.x*8u + (unsigned)w;
    unsigned tt=f;
    tt = ((tt>>p)<<(p+2))        | (tt & ((1u<<p)-1u));
    tt = ((tt>>(p+5))<<(p+7))    | (tt & ((1u<<(p+5))-1u));
    tt = ((tt>>(p+10))<<(p+12))  | (tt & ((1u<<(p+10))-1u));
    tt = ((tt>>(p+15))<<(p+17))  | (tt & ((1u<<(p+15))-1u));
    unsigned base=tt;
    __syncthreads();
    unsigned offs[8];
    #pragma unroll
    for (int t=0;t<8;t++){
        int e = l + 32*t;
        int i0 = e & 15, i1 = e >> 4;
        unsigned off =
            (unsigned)(((i0&1)|((i1&1)<<1)) << p) |
            (unsigned)((((i0>>1)&1)|(((i1>>1)&1)<<1)) << (p+5)) |
            (unsigned)((((i0>>2)&1)|(((i1>>2)&1)<<1)) << (p+10)) |
            (unsigned)((((i0>>3)&1)|(((i1>>3)&1)<<1)) << (p+15));
        offs[t]=off;
        Tsm[w][i1][i0] = psi[base+off];
    }
    __syncwarp();
    #pragma unroll
    for (int t=0;t<8;t++){
        int e = l + 32*t;
        int c = e & 15, o = e >> 4;
        float acc=0.f;
        #pragma unroll
        for (int k=0;k<16;k++) acc += Cs[o*16+k]*Tsm[w][k][c];
        Usm[w][o][c]=acc;
    }
    __syncwarp();
    #pragma unroll
    for (int t=0;t<8;t++){
        int e = l + 32*t;
        int i0 = e & 15, i1 = e >> 4;
        float acc=0.f;
        #pragma unroll
        for (int c=0;c<16;c++) acc += Cs[i0*16+c]*Usm[w][i1][c];
        psi[base+offs[t]] = acc;
    }
}

// ------------- v3: columns p=2,3,4 in one pass, in-place -------------
__global__ __launch_bounds__(256) void v3_kernel(float* __restrict__ psi){
    __shared__ float Cs[256];
    __shared__ float S[256*17 + 16];
    int t=threadIdx.x;
    Cs[t]=g_C16[t];
    unsigned f = blockIdx.x;  // 8 bits
    unsigned tt=f;
    tt = ((tt>>2)<<5)   | (tt & 3u);
    tt = ((tt>>7)<<10)  | (tt & 127u);
    tt = ((tt>>12)<<15) | (tt & 4095u);
    tt = ((tt>>17)<<20) | (tt & 131071u);
    unsigned base=tt;
    {
        int b=t>>4, c=t&15;
        unsigned offb = ((unsigned)(b&1)<<3)|((unsigned)((b>>1)&1)<<8)|((unsigned)((b>>2)&1)<<13)|((unsigned)((b>>3)&1)<<18);
        unsigned offc = ((unsigned)(c&1)<<4)|((unsigned)((c>>1)&1)<<9)|((unsigned)((c>>2)&1)<<14)|((unsigned)((c>>3)&1)<<19);
        unsigned bs = base + offb + offc;
        #pragma unroll
        for (int a=0;a<16;a++){
            unsigned offa = ((unsigned)(a&1)<<2)|((unsigned)((a>>1)&1)<<7)|((unsigned)((a>>2)&1)<<12)|((unsigned)((a>>3)&1)<<17);
            S[t*17 + a] = psi[bs + offa];
        }
    }
    __syncthreads();
    {
        float v[16], o[16];
        #pragma unroll
        for (int a=0;a<16;a++) v[a]=S[t*17+a];
        #pragma unroll
        for (int ap=0;ap<16;ap++){
            float acc=0.f;
            #pragma unroll
            for (int a=0;a<16;a++) acc += Cs[ap*16+a]*v[a];
            o[ap]=acc;
        }
        #pragma unroll
        for (int a=0;a<16;a++) S[t*17+a]=o[a];
    }
    __syncthreads();
    {
        int a=t>>4, c=t&15;
        float v[16], o[16];
        #pragma unroll
        for (int b=0;b<16;b++) v[b]=S[(b*16+c)*17 + a];
        #pragma unroll
        for (int bp=0;bp<16;bp++){
            float acc=0.f;
            #pragma unroll
            for (int b=0;b<16;b++) acc += Cs[bp*16+b]*v[b];
            o[bp]=acc;
        }
        #pragma unroll
        for (int b=0;b<16;b++) S[(b*16+c)*17 + a]=o[b];
    }
    __syncthreads();
    {
        int a=t&15, b=t>>4;
        float v[16], o[16];
        #pragma unroll
        for (int c=0;c<16;c++) v[c]=S[(b*16+c)*17 + a];
        #pragma unroll
        for (int cp=0;cp<16;cp++){
            float acc=0.f;
            #pragma unroll
            for (int c=0;c<16;c++) acc += Cs[cp*16+c]*v[c];
            o[cp]=acc;
        }
        #pragma unroll
        for (int c=0;c<16;c++) S[(b*16+c)*17 + a]=o[c];
    }
    __syncthreads();
    {
        int b=t>>4, c=t&15;
        unsigned offb = ((unsigned)(b&1)<<3)|((unsigned)((b>>1)&1)<<8)|((unsigned)((b>>2)&1)<<13)|((unsigned)((b>>3)&1)<<18);
        unsigned offc = ((unsigned)(c&1)<<4)|((unsigned)((c>>1)&1)<<9)|((unsigned)((c>>2)&1)<<14)|((unsigned)((c>>3)&1)<<19);
        unsigned bs = base + offb + offc;
        #pragma unroll
        for (int a=0;a<16;a++){
            unsigned offa = ((unsigned)(a&1)<<2)|((unsigned)((a>>1)&1)<<7)|((unsigned)((a>>2)&1)<<12)|((unsigned)((a>>3)&1)<<17);
            psi[bs + offa] = S[t*17 + a];
        }
    }
}

// ------------- gather 64 amplitudes -------------
__global__ void gather_kernel(const int* __restrict__ x, const float* __restrict__ psi,
                              float* __restrict__ out){
    int b = threadIdx.x;
    unsigned idx=0;
    #pragma unroll
    for (int j=0;j<20;j++) idx = (idx<<1) | (unsigned)x[b*20+j];
    out[b]=psi[idx];
}

extern "C" void kernel_launch(void* const* d_in, const int* in_sizes, int n_in,
                              void* d_out, int out_size){
    const int*   x    = (const int*)d_in[0];
    const float* peps = (const float*)d_in[1];
    const float* gate = (const float*)d_in[2];
    float* out = (float*)d_out;

    float *A,*Cm,*psi;
    cudaGetSymbolAddress((void**)&A,    g_A);
    cudaGetSymbolAddress((void**)&Cm,   g_Cm);
    cudaGetSymbolAddress((void**)&psi,  g_psi);

    prep_kernel<<<11,256>>>(peps, gate);
    kkprep_kernel<<<dim3(257,2),256>>>();
    fold23_kernel<<<dim3(256,2),256>>>();
    fold4_kernel<<<dim3(256,2),256>>>();

    sgemm_kernel<<<dim3(16,16),256>>>(A, Cm, psi);

    for (int sweep=0; sweep<5; sweep++){
        hhigh_kernel<<<128,256>>>(psi);   // bits [15-19] and [10-14]
        hlow_kernel<<<1024,256>>>(psi);   // bits [5-9] and [0-4]
        v3_kernel<<<256,256>>>(psi);      // columns at p=2,3,4
        v2_kernel<<<512,256>>>(psi, 0);   // columns at p=0,1
    }

    gather_kernel<<<1,64>>>(x, psi, out);
}